// round 10
// baseline (speedup 1.0000x reference)
#include <cuda_runtime.h>

#define N_ROWS   16384
#define D        1024
#define D4       (D / 4)          // 256 float4 per row
#define TEMPC    0.05f
#define EPSC     1e-8f

#define THREADS     256
#define WARPS_CTA   8
#define GRID        (N_ROWS / WARPS_CTA)   // 2048 CTAs, exactly 1 row per warp
#define CHUNKS      4                      // 4 iterations x (2+2) float4 loads
                                           // -> MLP_p1 = 4 (not 16): avoids
                                           // cross-CTA L1tex queue spread

__device__ float g_partial[GRID];
__device__ unsigned int g_done = 0;

__global__ __launch_bounds__(THREADS) void byol_chunked_kernel(
    const float4* __restrict__ a4, const float4* __restrict__ b4,
    float* __restrict__ out)
{
    const int t   = threadIdx.x;
    const int wid = t >> 5;
    const int lid = t & 31;

    const int  row  = blockIdx.x * WARPS_CTA + wid;
    const long base = (long)row * D4 + lid;

    float dot = 0.f, aa = 0.f, bb = 0.f;

    #pragma unroll 1                        // keep chunks separate in SASS
    for (int c = 0; c < CHUNKS; c++) {
        const long idx = base + 64 * c;
        const float4 av0 = a4[idx];
        const float4 av1 = a4[idx + 32];
        const float4 bv0 = b4[idx];
        const float4 bv1 = b4[idx + 32];

        dot += av0.x * bv0.x + av0.y * bv0.y + av0.z * bv0.z + av0.w * bv0.w;
        aa  += av0.x * av0.x + av0.y * av0.y + av0.z * av0.z + av0.w * av0.w;
        bb  += bv0.x * bv0.x + bv0.y * bv0.y + bv0.z * bv0.z + bv0.w * bv0.w;

        dot += av1.x * bv1.x + av1.y * bv1.y + av1.z * bv1.z + av1.w * bv1.w;
        aa  += av1.x * av1.x + av1.y * av1.y + av1.z * av1.z + av1.w * av1.w;
        bb  += bv1.x * bv1.x + bv1.y * bv1.y + bv1.z * bv1.z + bv1.w * bv1.w;
    }

    #pragma unroll
    for (int off = 16; off > 0; off >>= 1) {
        dot += __shfl_xor_sync(0xffffffffu, dot, off);
        aa  += __shfl_xor_sync(0xffffffffu, aa,  off);
        bb  += __shfl_xor_sync(0xffffffffu, bb,  off);
    }

    // CTA combine (fixed warp order -> deterministic), one partial per CTA
    __shared__ float s_warp[WARPS_CTA];
    __shared__ bool  s_last;
    if (lid == 0) {
        const float n1 = fmaxf(sqrtf(aa), EPSC);
        const float n2 = fmaxf(sqrtf(bb), EPSC);
        s_warp[wid] = 2.0f - 2.0f * (dot / (n1 * n2));
    }
    __syncthreads();

    if (t == 0) {
        float p = 0.f;
        #pragma unroll
        for (int w = 0; w < WARPS_CTA; w++) p += s_warp[w];
        g_partial[blockIdx.x] = p;
        __threadfence();
        const unsigned int prev = atomicAdd(&g_done, 1u);
        s_last = (prev == GRID - 1);
    }
    __syncthreads();

    // Last CTA: deterministic fixed-order reduce of 2048 partials
    if (s_last) {
        __shared__ float s[THREADS];
        float sum = 0.f;
        #pragma unroll
        for (int i = 0; i < GRID / THREADS; i++)       // 8 each, fixed order
            sum += g_partial[t + i * THREADS];
        s[t] = sum;
        __syncthreads();
        #pragma unroll
        for (int off = THREADS / 2; off > 0; off >>= 1) {
            if (t < off) s[t] += s[t + off];
            __syncthreads();
        }
        if (t == 0) {
            out[0] = s[0] / ((float)N_ROWS * TEMPC);
            g_done = 0;   // reset for graph replay
        }
    }
}

extern "C" void kernel_launch(void* const* d_in, const int* in_sizes, int n_in,
                              void* d_out, int out_size)
{
    const float4* a4 = (const float4*)d_in[0];  // online_output [16384,1024] f32
    const float4* b4 = (const float4*)d_in[1];  // target_output [16384,1024] f32
    float* out = (float*)d_out;

    byol_chunked_kernel<<<GRID, THREADS>>>(a4, b4, out);
}

// round 11
// speedup vs baseline: 1.0814x; 1.0814x over previous
#include <cuda_runtime.h>

#define N_ROWS   16384
#define D        1024
#define D4       (D / 4)          // 256 float4 per row
#define TEMPC    0.05f
#define EPSC     1e-8f

#define THREADS     256
#define WARPS_CTA   8
#define GRID        (N_ROWS / WARPS_CTA)   // 2048 CTAs, exactly 1 row per warp
#define F4_PER_LANE (D4 / 32)              // 8

__device__ float g_partial[GRID];
__device__ unsigned int g_done = 0;

__global__ __launch_bounds__(THREADS) void byol_ldcv_kernel(
    const float4* __restrict__ a4, const float4* __restrict__ b4,
    float* __restrict__ out)
{
    const int t   = threadIdx.x;
    const int wid = t >> 5;
    const int lid = t & 31;

    // Exactly one row per warp (R5 schedule: best so far)
    const int  row = blockIdx.x * WARPS_CTA + wid;
    const long idx = (long)row * D4 + lid;

    // LDG.E.CV.128: bypass L1 allocation (read-once stream).
    float4 av[F4_PER_LANE], bv[F4_PER_LANE];
    #pragma unroll
    for (int j = 0; j < F4_PER_LANE; j++) av[j] = __ldcv(&a4[idx + 32 * j]);
    #pragma unroll
    for (int j = 0; j < F4_PER_LANE; j++) bv[j] = __ldcv(&b4[idx + 32 * j]);

    float dot = 0.f, aa = 0.f, bb = 0.f;
    #pragma unroll
    for (int j = 0; j < F4_PER_LANE; j++) {
        dot += av[j].x * bv[j].x + av[j].y * bv[j].y
             + av[j].z * bv[j].z + av[j].w * bv[j].w;
        aa  += av[j].x * av[j].x + av[j].y * av[j].y
             + av[j].z * av[j].z + av[j].w * av[j].w;
        bb  += bv[j].x * bv[j].x + bv[j].y * bv[j].y
             + bv[j].z * bv[j].z + bv[j].w * bv[j].w;
    }

    #pragma unroll
    for (int off = 16; off > 0; off >>= 1) {
        dot += __shfl_xor_sync(0xffffffffu, dot, off);
        aa  += __shfl_xor_sync(0xffffffffu, aa,  off);
        bb  += __shfl_xor_sync(0xffffffffu, bb,  off);
    }

    // CTA combine (fixed warp order -> deterministic), one partial per CTA
    __shared__ float s_warp[WARPS_CTA];
    __shared__ bool  s_last;
    if (lid == 0) {
        const float n1 = fmaxf(sqrtf(aa), EPSC);
        const float n2 = fmaxf(sqrtf(bb), EPSC);
        s_warp[wid] = 2.0f - 2.0f * (dot / (n1 * n2));
    }
    __syncthreads();

    if (t == 0) {
        float p = 0.f;
        #pragma unroll
        for (int w = 0; w < WARPS_CTA; w++) p += s_warp[w];
        g_partial[blockIdx.x] = p;
        __threadfence();
        const unsigned int prev = atomicAdd(&g_done, 1u);
        s_last = (prev == GRID - 1);
    }
    __syncthreads();

    // Last CTA: deterministic fixed-order reduce of 2048 partials
    if (s_last) {
        __shared__ float s[THREADS];
        float sum = 0.f;
        #pragma unroll
        for (int i = 0; i < GRID / THREADS; i++)       // 8 each, fixed order
            sum += g_partial[t + i * THREADS];
        s[t] = sum;
        __syncthreads();
        #pragma unroll
        for (int off = THREADS / 2; off > 0; off >>= 1) {
            if (t < off) s[t] += s[t + off];
            __syncthreads();
        }
        if (t == 0) {
            out[0] = s[0] / ((float)N_ROWS * TEMPC);
            g_done = 0;   // reset for graph replay
        }
    }
}

extern "C" void kernel_launch(void* const* d_in, const int* in_sizes, int n_in,
                              void* d_out, int out_size)
{
    const float4* a4 = (const float4*)d_in[0];  // online_output [16384,1024] f32
    const float4* b4 = (const float4*)d_in[1];  // target_output [16384,1024] f32
    float* out = (float*)d_out;

    byol_ldcv_kernel<<<GRID, THREADS>>>(a4, b4, out);
}